// round 12
// baseline (speedup 1.0000x reference)
#include <cuda_runtime.h>
#include <cuda_bf16.h>
#include <math.h>
#include <stdint.h>

// Problem constants
#define BATCH   2
#define SEQ     2048
#define EMBED   1024
#define HEADS   16
#define HDIM    64
#define TOKENS  (BATCH * SEQ)        // 4096
#define QKV_COLS (3 * EMBED)         // 3072

// ---------------- scratch (device globals: allocation-free) ----------------
__device__ uint32_t g_qkv[(size_t)TOKENS * QKV_COLS];   // QKV, tf32 (Q pre-scaled)
__device__ uint32_t g_att[(size_t)TOKENS * EMBED];      // attention out, tf32
__device__ uint32_t g_x32[(size_t)TOKENS * EMBED];      // x, tf32
__device__ uint32_t g_wq32[(size_t)EMBED * QKV_COLS];   // W_qkv, tf32
__device__ uint32_t g_wp32[(size_t)EMBED * EMBED];      // W_proj, tf32

// ---------------- helpers ----------------
__device__ __forceinline__ uint32_t f2tf32(float x) {
    uint32_t r;
    asm("cvt.rna.tf32.f32 %0, %1;" : "=r"(r) : "f"(x));
    return r;
}
__device__ __forceinline__ uint4 cvt4(float4 v) {
    return make_uint4(f2tf32(v.x), f2tf32(v.y), f2tf32(v.z), f2tf32(v.w));
}
__device__ __forceinline__ void mma_tf32(float c[4],
                                         uint32_t a0, uint32_t a1, uint32_t a2, uint32_t a3,
                                         uint32_t b0, uint32_t b1) {
    asm volatile(
        "mma.sync.aligned.m16n8k8.row.col.f32.tf32.tf32.f32 "
        "{%0,%1,%2,%3}, {%4,%5,%6,%7}, {%8,%9}, {%0,%1,%2,%3};"
        : "+f"(c[0]), "+f"(c[1]), "+f"(c[2]), "+f"(c[3])
        : "r"(a0), "r"(a1), "r"(a2), "r"(a3), "r"(b0), "r"(b1));
}
__device__ __forceinline__ void cp_async16(void* smem_dst, const void* gmem_src) {
    uint32_t s = (uint32_t)__cvta_generic_to_shared(smem_dst);
    asm volatile("cp.async.cg.shared.global [%0], [%1], 16;\n" :: "r"(s), "l"(gmem_src));
}
#define CP_COMMIT() asm volatile("cp.async.commit_group;\n" ::: "memory")
#define CP_WAIT1()  asm volatile("cp.async.wait_group 1;\n" ::: "memory")

// ---------------- one-shot converter: fp32 -> tf32 bits ----------------
__global__ void cvt_tf32_kernel(const float4* __restrict__ src,
                                uint4* __restrict__ dst, int n4) {
    int i = blockIdx.x * blockDim.x + threadIdx.x;
    if (i < n4) dst[i] = cvt4(src[i]);
}

// ============================================================================
// tf32 GEMM, 3-stage cp.async pipeline, all-tf32 inputs (unchanged from R10).
// ============================================================================
#define GAS 36
#define GBS 136
#define A_WORDS (128 * GAS)              // 4608
#define B_WORDS (32 * GBS)               // 4352
#define STG_WORDS (A_WORDS + B_WORDS)    // 8960
#define GEMM_SMEM (3 * STG_WORDS * 4)    // 107520 B

__global__ __launch_bounds__(256, 2) void gemm_tf32(const uint32_t* __restrict__ A,
                                                    const uint32_t* __restrict__ B,
                                                    const float* __restrict__ bias,
                                                    void* __restrict__ Cout,
                                                    int M, int N, int K, int mode) {
    extern __shared__ uint32_t dsm[];

    const int tid  = threadIdx.x;
    const int wid  = tid >> 5;
    const int lane = tid & 31;
    const int lq   = lane >> 2;
    const int lr   = lane & 3;

    const int wrow = (wid & 3) * 32;
    const int wcol = (wid >> 2) * 64;
    const int rowBase = blockIdx.y * 128;
    const int colBase = blockIdx.x * 128;

    float c[2][8][4];
#pragma unroll
    for (int mt = 0; mt < 2; mt++)
#pragma unroll
        for (int nt = 0; nt < 8; nt++)
#pragma unroll
            for (int i = 0; i < 4; i++) c[mt][nt][i] = 0.f;

    auto load_tile = [&](int stg, int k0) {
        uint32_t* as = dsm + stg * STG_WORDS;
        uint32_t* bs = as + A_WORDS;
#pragma unroll
        for (int t = 0; t < 4; t++) {
            int idx = tid + t * 256;
            int r  = idx >> 3;
            int c4 = idx & 7;
            cp_async16(&as[r * GAS + c4 * 4],
                       &A[(size_t)(rowBase + r) * K + k0 + c4 * 4]);
        }
#pragma unroll
        for (int t = 0; t < 4; t++) {
            int idx = tid + t * 256;
            int kk = idx >> 5;
            int c4 = idx & 31;
            cp_async16(&bs[kk * GBS + c4 * 4],
                       &B[(size_t)(k0 + kk) * N + colBase + c4 * 4]);
        }
    };

    const int nk = K / 32;
    load_tile(0, 0);
    CP_COMMIT();
    load_tile(1, 32);
    CP_COMMIT();

    for (int ki = 0; ki < nk; ki++) {
        CP_WAIT1();
        __syncthreads();
        if (ki + 2 < nk) load_tile((ki + 2) % 3, (ki + 2) * 32);
        CP_COMMIT();

        const uint32_t* as = dsm + (ki % 3) * STG_WORDS;
        const uint32_t* bs = as + A_WORDS;
#pragma unroll
        for (int ks = 0; ks < 4; ks++) {
            uint32_t a[2][4];
#pragma unroll
            for (int mt = 0; mt < 2; mt++) {
                int rb = wrow + mt * 16;
                a[mt][0] = as[(rb + lq) * GAS + ks * 8 + lr];
                a[mt][1] = as[(rb + lq + 8) * GAS + ks * 8 + lr];
                a[mt][2] = as[(rb + lq) * GAS + ks * 8 + lr + 4];
                a[mt][3] = as[(rb + lq + 8) * GAS + ks * 8 + lr + 4];
            }
#pragma unroll
            for (int nt = 0; nt < 8; nt++) {
                int cb = wcol + nt * 8 + lq;
                uint32_t b0 = bs[(ks * 8 + lr) * GBS + cb];
                uint32_t b1 = bs[(ks * 8 + lr + 4) * GBS + cb];
                mma_tf32(c[0][nt], a[0][0], a[0][1], a[0][2], a[0][3], b0, b1);
                mma_tf32(c[1][nt], a[1][0], a[1][1], a[1][2], a[1][3], b0, b1);
            }
        }
        __syncthreads();
    }

    const float qscale = (mode == 1 && colBase < EMBED) ? 0.125f : 1.0f;
#pragma unroll
    for (int mt = 0; mt < 2; mt++) {
        int r0 = rowBase + wrow + mt * 16 + lq;
#pragma unroll
        for (int nt = 0; nt < 8; nt++) {
            int cc = colBase + wcol + nt * 8 + 2 * lr;
            float b0 = bias[cc], b1 = bias[cc + 1];
            float v00 = (c[mt][nt][0] + b0) * qscale;
            float v01 = (c[mt][nt][1] + b1) * qscale;
            float v10 = (c[mt][nt][2] + b0) * qscale;
            float v11 = (c[mt][nt][3] + b1) * qscale;
            if (mode == 1) {
                uint32_t* Cu = (uint32_t*)Cout;
                *(uint2*)&Cu[(size_t)r0 * N + cc] = make_uint2(f2tf32(v00), f2tf32(v01));
                *(uint2*)&Cu[(size_t)(r0 + 8) * N + cc] = make_uint2(f2tf32(v10), f2tf32(v11));
            } else {
                float* Cf = (float*)Cout;
                *(float2*)&Cf[(size_t)r0 * N + cc] = make_float2(v00, v01);
                *(float2*)&Cf[(size_t)(r0 + 8) * N + cc] = make_float2(v10, v11);
            }
        }
    }
}

// ============================================================================
// tf32 mma.sync flash attention — 4 warps, warp owns 32 Q-rows (2 m-tiles).
// Exact softmax (no online max), deferred row-sum reduction.
// P never touches smem: S C-fragments are re-shaped into PV A-fragments with
// shfl.idx lane permutations.  smem = Qs+Ks+Vs only (70.7 KB) -> 3 CTAs/SM.
// grid (B*H, SEQ/128), 128 threads.
// ============================================================================
#define QS_S 68
#define KS_S 68
#define VS_S 72

__global__ __launch_bounds__(128, 3) void flash_attn_tc(const uint32_t* __restrict__ qkv,
                                                        uint32_t* __restrict__ out) {
    extern __shared__ uint32_t sm[];
    uint32_t* Qs = sm;                        // 128*68
    uint32_t* Ks = Qs + 128 * QS_S;           // 64*68
    uint32_t* Vs = Ks + 64 * KS_S;            // 64*72

    const int tid  = threadIdx.x;
    const int wid  = tid >> 5;                // 0..3
    const int lane = tid & 31;
    const int lq   = lane >> 2;
    const int lr   = lane & 3;

    const int bh = blockIdx.x;
    const int b  = bh >> 4;
    const int h  = bh & 15;
    const int qbase = blockIdx.y * 128;
    const size_t tokBase = (size_t)b * SEQ;
    const int wrow = wid * 32;                // warp owns rows wrow..wrow+31

    // shfl source lanes for the C->A fragment permutation
    const int src0 = lq * 4 + (lr >> 1);
    const int src1 = src0 + 2;
    const bool oddc = (lr & 1);

    // Load Q tile (tf32, pre-scaled) — pure copy
#pragma unroll
    for (int t = 0; t < 16; t++) {
        int idx = tid + t * 128;
        int r  = idx >> 4;
        int c4 = idx & 15;
        *(uint4*)&Qs[r * QS_S + c4 * 4] =
            *(const uint4*)&qkv[(tokBase + qbase + r) * QKV_COLS + h * HDIM + c4 * 4];
    }

    float o[2][8][4];
#pragma unroll
    for (int mt = 0; mt < 2; mt++)
#pragma unroll
        for (int nt = 0; nt < 8; nt++)
#pragma unroll
            for (int i = 0; i < 4; i++) o[mt][nt][i] = 0.f;
    float psum[2][2] = {{0.f, 0.f}, {0.f, 0.f}};

    for (int kb = 0; kb < SEQ; kb += 64) {
        __syncthreads();
#pragma unroll
        for (int t = 0; t < 8; t++) {
            int idx = tid + t * 128;
            int r  = idx >> 4;
            int c4 = idx & 15;
            size_t base = (tokBase + kb + r) * QKV_COLS + h * HDIM + c4 * 4;
            *(uint4*)&Ks[r * KS_S + c4 * 4] = *(const uint4*)&qkv[base + EMBED];
            *(uint4*)&Vs[r * VS_S + c4 * 4] = *(const uint4*)&qkv[base + 2 * EMBED];
        }
        __syncthreads();

        // S = Q @ K^T  (32 x 64 per warp, B-fragments shared across m-tiles)
        float s[2][8][4];
#pragma unroll
        for (int mt = 0; mt < 2; mt++)
#pragma unroll
            for (int nt = 0; nt < 8; nt++)
#pragma unroll
                for (int i = 0; i < 4; i++) s[mt][nt][i] = 0.f;

#pragma unroll
        for (int ks = 0; ks < 8; ks++) {
            uint32_t a[2][4];
#pragma unroll
            for (int mt = 0; mt < 2; mt++) {
                int rb = wrow + mt * 16;
                a[mt][0] = Qs[(rb + lq) * QS_S + ks * 8 + lr];
                a[mt][1] = Qs[(rb + lq + 8) * QS_S + ks * 8 + lr];
                a[mt][2] = Qs[(rb + lq) * QS_S + ks * 8 + lr + 4];
                a[mt][3] = Qs[(rb + lq + 8) * QS_S + ks * 8 + lr + 4];
            }
#pragma unroll
            for (int nt = 0; nt < 8; nt++) {
                uint32_t b0 = Ks[(nt * 8 + lq) * KS_S + ks * 8 + lr];
                uint32_t b1 = Ks[(nt * 8 + lq) * KS_S + ks * 8 + lr + 4];
                mma_tf32(s[0][nt], a[0][0], a[0][1], a[0][2], a[0][3], b0, b1);
                mma_tf32(s[1][nt], a[1][0], a[1][1], a[1][2], a[1][3], b0, b1);
            }
        }

        // P = exp(S), tf32 bits in registers (C-fragment layout); row partials.
        uint32_t pu[2][8][4];
#pragma unroll
        for (int mt = 0; mt < 2; mt++) {
#pragma unroll
            for (int nt = 0; nt < 8; nt++) {
                float p0 = __expf(s[mt][nt][0]);
                float p1 = __expf(s[mt][nt][1]);
                float p2 = __expf(s[mt][nt][2]);
                float p3 = __expf(s[mt][nt][3]);
                psum[mt][0] += p0 + p1;
                psum[mt][1] += p2 + p3;
                pu[mt][nt][0] = f2tf32(p0);
                pu[mt][nt][1] = f2tf32(p1);
                pu[mt][nt][2] = f2tf32(p2);
                pu[mt][nt][3] = f2tf32(p3);
            }
        }

        // O += P @ V : A-fragments built from pu via lane shuffles (no smem)
#pragma unroll
        for (int ks = 0; ks < 8; ks++) {
            uint32_t a[2][4];
#pragma unroll
            for (int mt = 0; mt < 2; mt++) {
                uint32_t x0 = __shfl_sync(0xffffffffu, pu[mt][ks][0], src0);
                uint32_t x1 = __shfl_sync(0xffffffffu, pu[mt][ks][1], src0);
                a[mt][0] = oddc ? x1 : x0;
                uint32_t y0 = __shfl_sync(0xffffffffu, pu[mt][ks][2], src0);
                uint32_t y1 = __shfl_sync(0xffffffffu, pu[mt][ks][3], src0);
                a[mt][1] = oddc ? y1 : y0;
                uint32_t z0 = __shfl_sync(0xffffffffu, pu[mt][ks][0], src1);
                uint32_t z1 = __shfl_sync(0xffffffffu, pu[mt][ks][1], src1);
                a[mt][2] = oddc ? z1 : z0;
                uint32_t w0 = __shfl_sync(0xffffffffu, pu[mt][ks][2], src1);
                uint32_t w1 = __shfl_sync(0xffffffffu, pu[mt][ks][3], src1);
                a[mt][3] = oddc ? w1 : w0;
            }
#pragma unroll
            for (int nt = 0; nt < 8; nt++) {
                uint32_t b0 = Vs[(ks * 8 + lr) * VS_S + nt * 8 + lq];
                uint32_t b1 = Vs[(ks * 8 + lr + 4) * VS_S + nt * 8 + lq];
                mma_tf32(o[0][nt], a[0][0], a[0][1], a[0][2], a[0][3], b0, b1);
                mma_tf32(o[1][nt], a[1][0], a[1][1], a[1][2], a[1][3], b0, b1);
            }
        }
    }

    // Epilogue: one-shot row-sum reduction across the 4 lr lanes, normalize.
#pragma unroll
    for (int mt = 0; mt < 2; mt++) {
#pragma unroll
        for (int half = 0; half < 2; half++) {
            psum[mt][half] += __shfl_xor_sync(0xffffffffu, psum[mt][half], 1);
            psum[mt][half] += __shfl_xor_sync(0xffffffffu, psum[mt][half], 2);
        }
        float inv0 = 1.0f / psum[mt][0];
        float inv1 = 1.0f / psum[mt][1];
        size_t row0 = tokBase + qbase + wrow + mt * 16 + lq;
#pragma unroll
        for (int nt = 0; nt < 8; nt++) {
            int cc = h * HDIM + nt * 8 + 2 * lr;
            *(uint2*)&out[row0 * EMBED + cc] =
                make_uint2(f2tf32(o[mt][nt][0] * inv0), f2tf32(o[mt][nt][1] * inv0));
            *(uint2*)&out[(row0 + 8) * EMBED + cc] =
                make_uint2(f2tf32(o[mt][nt][2] * inv1), f2tf32(o[mt][nt][3] * inv1));
        }
    }
}

// ---------------- launch ----------------
extern "C" void kernel_launch(void* const* d_in, const int* in_sizes, int n_in,
                              void* d_out, int out_size) {
    const float* x      = (const float*)d_in[0];
    const float* W_qkv  = (const float*)d_in[1];
    const float* b_qkv  = (const float*)d_in[2];
    const float* W_proj = (const float*)d_in[3];
    const float* b_proj = (const float*)d_in[4];
    float* out          = (float*)d_out;

    uint32_t *qkv, *att, *x32, *wq32, *wp32;
    cudaGetSymbolAddress((void**)&qkv,  g_qkv);
    cudaGetSymbolAddress((void**)&att,  g_att);
    cudaGetSymbolAddress((void**)&x32,  g_x32);
    cudaGetSymbolAddress((void**)&wq32, g_wq32);
    cudaGetSymbolAddress((void**)&wp32, g_wp32);

    const int attn_smem = (128 * QS_S + 64 * KS_S + 64 * VS_S) * 4;   // 70656
    cudaFuncSetAttribute(gemm_tf32,
                         cudaFuncAttributeMaxDynamicSharedMemorySize, GEMM_SMEM);
    cudaFuncSetAttribute(flash_attn_tc,
                         cudaFuncAttributeMaxDynamicSharedMemorySize, attn_smem);

    // 0) one-shot fp32 -> tf32 conversions
    {
        int n4;
        n4 = TOKENS * EMBED / 4;
        cvt_tf32_kernel<<<(n4 + 255) / 256, 256>>>((const float4*)x, (uint4*)x32, n4);
        n4 = EMBED * QKV_COLS / 4;
        cvt_tf32_kernel<<<(n4 + 255) / 256, 256>>>((const float4*)W_qkv, (uint4*)wq32, n4);
        n4 = EMBED * EMBED / 4;
        cvt_tf32_kernel<<<(n4 + 255) / 256, 256>>>((const float4*)W_proj, (uint4*)wp32, n4);
    }
    // 1) QKV GEMM + bias -> tf32 qkv (Q pre-scaled by 0.125)
    {
        dim3 grid(QKV_COLS / 128, TOKENS / 128);
        gemm_tf32<<<grid, 256, GEMM_SMEM>>>(x32, wq32, b_qkv, qkv,
                                            TOKENS, QKV_COLS, EMBED, 1);
    }
    // 2) Flash attention -> tf32 att
    {
        dim3 grid(BATCH * HEADS, SEQ / 128);
        flash_attn_tc<<<grid, 128, attn_smem>>>(qkv, att);
    }
    // 3) Output projection + bias -> fp32 out
    {
        dim3 grid(EMBED / 128, TOKENS / 128);
        gemm_tf32<<<grid, 256, GEMM_SMEM>>>(att, wp32, b_proj, out,
                                            TOKENS, EMBED, EMBED, 0);
    }
}

// round 13
// speedup vs baseline: 1.0674x; 1.0674x over previous
#include <cuda_runtime.h>
#include <cuda_bf16.h>
#include <math.h>
#include <stdint.h>

// Problem constants
#define BATCH   2
#define SEQ     2048
#define EMBED   1024
#define HEADS   16
#define HDIM    64
#define TOKENS  (BATCH * SEQ)        // 4096
#define QKV_COLS (3 * EMBED)         // 3072

// ---------------- scratch (device globals: allocation-free) ----------------
__device__ uint32_t g_qkv[(size_t)TOKENS * QKV_COLS];   // QKV, tf32 (Q pre-scaled)
__device__ uint32_t g_att[(size_t)TOKENS * EMBED];      // attention out, tf32
__device__ uint32_t g_x32[(size_t)TOKENS * EMBED];      // x, tf32
__device__ uint32_t g_wq32[(size_t)EMBED * QKV_COLS];   // W_qkv, tf32
__device__ uint32_t g_wp32[(size_t)EMBED * EMBED];      // W_proj, tf32

// ---------------- helpers ----------------
__device__ __forceinline__ uint32_t f2tf32(float x) {
    uint32_t r;
    asm("cvt.rna.tf32.f32 %0, %1;" : "=r"(r) : "f"(x));
    return r;
}
__device__ __forceinline__ uint4 cvt4(float4 v) {
    return make_uint4(f2tf32(v.x), f2tf32(v.y), f2tf32(v.z), f2tf32(v.w));
}
__device__ __forceinline__ void mma_tf32(float c[4],
                                         uint32_t a0, uint32_t a1, uint32_t a2, uint32_t a3,
                                         uint32_t b0, uint32_t b1) {
    asm volatile(
        "mma.sync.aligned.m16n8k8.row.col.f32.tf32.tf32.f32 "
        "{%0,%1,%2,%3}, {%4,%5,%6,%7}, {%8,%9}, {%0,%1,%2,%3};"
        : "+f"(c[0]), "+f"(c[1]), "+f"(c[2]), "+f"(c[3])
        : "r"(a0), "r"(a1), "r"(a2), "r"(a3), "r"(b0), "r"(b1));
}
__device__ __forceinline__ void cp_async16(void* smem_dst, const void* gmem_src) {
    uint32_t s = (uint32_t)__cvta_generic_to_shared(smem_dst);
    asm volatile("cp.async.cg.shared.global [%0], [%1], 16;\n" :: "r"(s), "l"(gmem_src));
}
#define CP_COMMIT() asm volatile("cp.async.commit_group;\n" ::: "memory")
#define CP_WAIT1()  asm volatile("cp.async.wait_group 1;\n" ::: "memory")

// ---------------- one-shot converter: fp32 -> tf32 bits ----------------
__global__ void cvt_tf32_kernel(const float4* __restrict__ src,
                                uint4* __restrict__ dst, int n4) {
    int i = blockIdx.x * blockDim.x + threadIdx.x;
    if (i < n4) dst[i] = cvt4(src[i]);
}

// ============================================================================
// tf32 GEMM, 3-stage cp.async pipeline, all-tf32 inputs (unchanged from R10).
// ============================================================================
#define GAS 36
#define GBS 136
#define A_WORDS (128 * GAS)              // 4608
#define B_WORDS (32 * GBS)               // 4352
#define STG_WORDS (A_WORDS + B_WORDS)    // 8960
#define GEMM_SMEM (3 * STG_WORDS * 4)    // 107520 B

__global__ __launch_bounds__(256, 2) void gemm_tf32(const uint32_t* __restrict__ A,
                                                    const uint32_t* __restrict__ B,
                                                    const float* __restrict__ bias,
                                                    void* __restrict__ Cout,
                                                    int M, int N, int K, int mode) {
    extern __shared__ uint32_t dsm[];

    const int tid  = threadIdx.x;
    const int wid  = tid >> 5;
    const int lane = tid & 31;
    const int lq   = lane >> 2;
    const int lr   = lane & 3;

    const int wrow = (wid & 3) * 32;
    const int wcol = (wid >> 2) * 64;
    const int rowBase = blockIdx.y * 128;
    const int colBase = blockIdx.x * 128;

    float c[2][8][4];
#pragma unroll
    for (int mt = 0; mt < 2; mt++)
#pragma unroll
        for (int nt = 0; nt < 8; nt++)
#pragma unroll
            for (int i = 0; i < 4; i++) c[mt][nt][i] = 0.f;

    auto load_tile = [&](int stg, int k0) {
        uint32_t* as = dsm + stg * STG_WORDS;
        uint32_t* bs = as + A_WORDS;
#pragma unroll
        for (int t = 0; t < 4; t++) {
            int idx = tid + t * 256;
            int r  = idx >> 3;
            int c4 = idx & 7;
            cp_async16(&as[r * GAS + c4 * 4],
                       &A[(size_t)(rowBase + r) * K + k0 + c4 * 4]);
        }
#pragma unroll
        for (int t = 0; t < 4; t++) {
            int idx = tid + t * 256;
            int kk = idx >> 5;
            int c4 = idx & 31;
            cp_async16(&bs[kk * GBS + c4 * 4],
                       &B[(size_t)(k0 + kk) * N + colBase + c4 * 4]);
        }
    };

    const int nk = K / 32;
    load_tile(0, 0);
    CP_COMMIT();
    load_tile(1, 32);
    CP_COMMIT();

    for (int ki = 0; ki < nk; ki++) {
        CP_WAIT1();
        __syncthreads();
        if (ki + 2 < nk) load_tile((ki + 2) % 3, (ki + 2) * 32);
        CP_COMMIT();

        const uint32_t* as = dsm + (ki % 3) * STG_WORDS;
        const uint32_t* bs = as + A_WORDS;
#pragma unroll
        for (int ks = 0; ks < 4; ks++) {
            uint32_t a[2][4];
#pragma unroll
            for (int mt = 0; mt < 2; mt++) {
                int rb = wrow + mt * 16;
                a[mt][0] = as[(rb + lq) * GAS + ks * 8 + lr];
                a[mt][1] = as[(rb + lq + 8) * GAS + ks * 8 + lr];
                a[mt][2] = as[(rb + lq) * GAS + ks * 8 + lr + 4];
                a[mt][3] = as[(rb + lq + 8) * GAS + ks * 8 + lr + 4];
            }
#pragma unroll
            for (int nt = 0; nt < 8; nt++) {
                int cb = wcol + nt * 8 + lq;
                uint32_t b0 = bs[(ks * 8 + lr) * GBS + cb];
                uint32_t b1 = bs[(ks * 8 + lr + 4) * GBS + cb];
                mma_tf32(c[0][nt], a[0][0], a[0][1], a[0][2], a[0][3], b0, b1);
                mma_tf32(c[1][nt], a[1][0], a[1][1], a[1][2], a[1][3], b0, b1);
            }
        }
        __syncthreads();
    }

    const float qscale = (mode == 1 && colBase < EMBED) ? 0.125f : 1.0f;
#pragma unroll
    for (int mt = 0; mt < 2; mt++) {
        int r0 = rowBase + wrow + mt * 16 + lq;
#pragma unroll
        for (int nt = 0; nt < 8; nt++) {
            int cc = colBase + wcol + nt * 8 + 2 * lr;
            float b0 = bias[cc], b1 = bias[cc + 1];
            float v00 = (c[mt][nt][0] + b0) * qscale;
            float v01 = (c[mt][nt][1] + b1) * qscale;
            float v10 = (c[mt][nt][2] + b0) * qscale;
            float v11 = (c[mt][nt][3] + b1) * qscale;
            if (mode == 1) {
                uint32_t* Cu = (uint32_t*)Cout;
                *(uint2*)&Cu[(size_t)r0 * N + cc] = make_uint2(f2tf32(v00), f2tf32(v01));
                *(uint2*)&Cu[(size_t)(r0 + 8) * N + cc] = make_uint2(f2tf32(v10), f2tf32(v11));
            } else {
                float* Cf = (float*)Cout;
                *(float2*)&Cf[(size_t)r0 * N + cc] = make_float2(v00, v01);
                *(float2*)&Cf[(size_t)(r0 + 8) * N + cc] = make_float2(v10, v11);
            }
        }
    }
}

// ============================================================================
// tf32 mma.sync flash attention — 4 warps, warp owns 32 Q-rows (2 m-tiles).
// Exact softmax (no online max), deferred row-sum reduction (R10 structure).
// NEW: split K/V cp.async phasing with the SAME two buffers:
//   Ks is dead after S, Vs is dead after PV, so
//   - during S_i  (reads Ks) the V_i load streams into Vs,
//   - during PV_i (reads Vs) the K_{i+1} load streams into Ks.
// Zero extra smem; 105.5 KB -> still 2 CTAs/SM.
// grid (B*H, SEQ/128), 128 threads.
// ============================================================================
#define QS_S 68
#define KS_S 68
#define PS_S 68
#define VS_S 72

__global__ __launch_bounds__(128) void flash_attn_tc(const uint32_t* __restrict__ qkv,
                                                     uint32_t* __restrict__ out) {
    extern __shared__ uint32_t sm[];
    uint32_t* Qs = sm;                        // 128*68
    uint32_t* Ks = Qs + 128 * QS_S;           // 64*68
    uint32_t* Vs = Ks + 64 * KS_S;            // 64*72
    uint32_t* Ps = Vs + 64 * VS_S;            // 128*68

    const int tid  = threadIdx.x;
    const int wid  = tid >> 5;                // 0..3
    const int lane = tid & 31;
    const int lq   = lane >> 2;
    const int lr   = lane & 3;

    const int bh = blockIdx.x;
    const int b  = bh >> 4;
    const int h  = bh & 15;
    const int qbase = blockIdx.y * 128;
    const size_t tokBase = (size_t)b * SEQ;
    const int wrow = wid * 32;                // warp owns rows wrow..wrow+31

    auto load_k = [&](int kb) {
#pragma unroll
        for (int t = 0; t < 8; t++) {
            int idx = tid + t * 128;
            int r  = idx >> 4;
            int c4 = idx & 15;
            cp_async16(&Ks[r * KS_S + c4 * 4],
                       &qkv[(tokBase + kb + r) * QKV_COLS + h * HDIM + EMBED + c4 * 4]);
        }
    };
    auto load_v = [&](int kb) {
#pragma unroll
        for (int t = 0; t < 8; t++) {
            int idx = tid + t * 128;
            int r  = idx >> 4;
            int c4 = idx & 15;
            cp_async16(&Vs[r * VS_S + c4 * 4],
                       &qkv[(tokBase + kb + r) * QKV_COLS + h * HDIM + 2 * EMBED + c4 * 4]);
        }
    };

    // prologue: K_0 in flight, then Q tile copy (overlaps the K_0 load)
    load_k(0);
    CP_COMMIT();
#pragma unroll
    for (int t = 0; t < 16; t++) {
        int idx = tid + t * 128;
        int r  = idx >> 4;
        int c4 = idx & 15;
        *(uint4*)&Qs[r * QS_S + c4 * 4] =
            *(const uint4*)&qkv[(tokBase + qbase + r) * QKV_COLS + h * HDIM + c4 * 4];
    }

    float o[2][8][4];
#pragma unroll
    for (int mt = 0; mt < 2; mt++)
#pragma unroll
        for (int nt = 0; nt < 8; nt++)
#pragma unroll
            for (int i = 0; i < 4; i++) o[mt][nt][i] = 0.f;
    float psum[2][2] = {{0.f, 0.f}, {0.f, 0.f}};

    const int niter = SEQ / 64;   // 32
    for (int it = 0; it < niter; it++) {
        int kb = it * 64;
        // Vs free (PV_{i-1} fully read it); also covers Qs visibility on it=0
        __syncthreads();
        load_v(kb);
        CP_COMMIT();
        CP_WAIT1();          // K_i (older group) has landed; V_i may be in flight
        __syncthreads();

        // S = Q @ K^T  (32 x 64 per warp, B-fragments shared across m-tiles)
        float s[2][8][4];
#pragma unroll
        for (int mt = 0; mt < 2; mt++)
#pragma unroll
            for (int nt = 0; nt < 8; nt++)
#pragma unroll
                for (int i = 0; i < 4; i++) s[mt][nt][i] = 0.f;

#pragma unroll
        for (int ks = 0; ks < 8; ks++) {
            uint32_t a[2][4];
#pragma unroll
            for (int mt = 0; mt < 2; mt++) {
                int rb = wrow + mt * 16;
                a[mt][0] = Qs[(rb + lq) * QS_S + ks * 8 + lr];
                a[mt][1] = Qs[(rb + lq + 8) * QS_S + ks * 8 + lr];
                a[mt][2] = Qs[(rb + lq) * QS_S + ks * 8 + lr + 4];
                a[mt][3] = Qs[(rb + lq + 8) * QS_S + ks * 8 + lr + 4];
            }
#pragma unroll
            for (int nt = 0; nt < 8; nt++) {
                uint32_t b0 = Ks[(nt * 8 + lq) * KS_S + ks * 8 + lr];
                uint32_t b1 = Ks[(nt * 8 + lq) * KS_S + ks * 8 + lr + 4];
                mma_tf32(s[0][nt], a[0][0], a[0][1], a[0][2], a[0][3], b0, b1);
                mma_tf32(s[1][nt], a[1][0], a[1][1], a[1][2], a[1][3], b0, b1);
            }
        }

        // P = exp(S) — exact softmax numerator; accumulate row partials
#pragma unroll
        for (int mt = 0; mt < 2; mt++) {
            int r0 = wrow + mt * 16 + lq;
#pragma unroll
            for (int nt = 0; nt < 8; nt++) {
                float p0 = __expf(s[mt][nt][0]);
                float p1 = __expf(s[mt][nt][1]);
                float p2 = __expf(s[mt][nt][2]);
                float p3 = __expf(s[mt][nt][3]);
                psum[mt][0] += p0 + p1;
                psum[mt][1] += p2 + p3;
                int cc = nt * 8 + 2 * lr;
                *(uint2*)&Ps[r0 * PS_S + cc]       = make_uint2(f2tf32(p0), f2tf32(p1));
                *(uint2*)&Ps[(r0 + 8) * PS_S + cc] = make_uint2(f2tf32(p2), f2tf32(p3));
            }
        }

        // All warps done reading Ks; K_{i+1} can stream in during PV.
        __syncthreads();
        if (it + 1 < niter) load_k(kb + 64);
        CP_COMMIT();
        CP_WAIT1();          // V_i (older group) has landed; K_{i+1} in flight
        __syncthreads();

        // O += P @ V
#pragma unroll
        for (int ks = 0; ks < 8; ks++) {
            uint32_t a[2][4];
#pragma unroll
            for (int mt = 0; mt < 2; mt++) {
                int rb = wrow + mt * 16;
                a[mt][0] = Ps[(rb + lq) * PS_S + ks * 8 + lr];
                a[mt][1] = Ps[(rb + lq + 8) * PS_S + ks * 8 + lr];
                a[mt][2] = Ps[(rb + lq) * PS_S + ks * 8 + lr + 4];
                a[mt][3] = Ps[(rb + lq + 8) * PS_S + ks * 8 + lr + 4];
            }
#pragma unroll
            for (int nt = 0; nt < 8; nt++) {
                uint32_t b0 = Vs[(ks * 8 + lr) * VS_S + nt * 8 + lq];
                uint32_t b1 = Vs[(ks * 8 + lr + 4) * VS_S + nt * 8 + lq];
                mma_tf32(o[0][nt], a[0][0], a[0][1], a[0][2], a[0][3], b0, b1);
                mma_tf32(o[1][nt], a[1][0], a[1][1], a[1][2], a[1][3], b0, b1);
            }
        }
    }

    // Epilogue: one-shot row-sum reduction across the 4 lr lanes, normalize.
#pragma unroll
    for (int mt = 0; mt < 2; mt++) {
#pragma unroll
        for (int half = 0; half < 2; half++) {
            psum[mt][half] += __shfl_xor_sync(0xffffffffu, psum[mt][half], 1);
            psum[mt][half] += __shfl_xor_sync(0xffffffffu, psum[mt][half], 2);
        }
        float inv0 = 1.0f / psum[mt][0];
        float inv1 = 1.0f / psum[mt][1];
        size_t row0 = tokBase + qbase + wrow + mt * 16 + lq;
#pragma unroll
        for (int nt = 0; nt < 8; nt++) {
            int cc = h * HDIM + nt * 8 + 2 * lr;
            *(uint2*)&out[row0 * EMBED + cc] =
                make_uint2(f2tf32(o[mt][nt][0] * inv0), f2tf32(o[mt][nt][1] * inv0));
            *(uint2*)&out[(row0 + 8) * EMBED + cc] =
                make_uint2(f2tf32(o[mt][nt][2] * inv1), f2tf32(o[mt][nt][3] * inv1));
        }
    }
}

// ---------------- launch ----------------
extern "C" void kernel_launch(void* const* d_in, const int* in_sizes, int n_in,
                              void* d_out, int out_size) {
    const float* x      = (const float*)d_in[0];
    const float* W_qkv  = (const float*)d_in[1];
    const float* b_qkv  = (const float*)d_in[2];
    const float* W_proj = (const float*)d_in[3];
    const float* b_proj = (const float*)d_in[4];
    float* out          = (float*)d_out;

    uint32_t *qkv, *att, *x32, *wq32, *wp32;
    cudaGetSymbolAddress((void**)&qkv,  g_qkv);
    cudaGetSymbolAddress((void**)&att,  g_att);
    cudaGetSymbolAddress((void**)&x32,  g_x32);
    cudaGetSymbolAddress((void**)&wq32, g_wq32);
    cudaGetSymbolAddress((void**)&wp32, g_wp32);

    const int attn_smem = (128 * QS_S * 2 + 64 * KS_S + 64 * VS_S) * 4;   // 105472
    cudaFuncSetAttribute(gemm_tf32,
                         cudaFuncAttributeMaxDynamicSharedMemorySize, GEMM_SMEM);
    cudaFuncSetAttribute(flash_attn_tc,
                         cudaFuncAttributeMaxDynamicSharedMemorySize, attn_smem);

    // 0) one-shot fp32 -> tf32 conversions
    {
        int n4;
        n4 = TOKENS * EMBED / 4;
        cvt_tf32_kernel<<<(n4 + 255) / 256, 256>>>((const float4*)x, (uint4*)x32, n4);
        n4 = EMBED * QKV_COLS / 4;
        cvt_tf32_kernel<<<(n4 + 255) / 256, 256>>>((const float4*)W_qkv, (uint4*)wq32, n4);
        n4 = EMBED * EMBED / 4;
        cvt_tf32_kernel<<<(n4 + 255) / 256, 256>>>((const float4*)W_proj, (uint4*)wp32, n4);
    }
    // 1) QKV GEMM + bias -> tf32 qkv (Q pre-scaled by 0.125)
    {
        dim3 grid(QKV_COLS / 128, TOKENS / 128);
        gemm_tf32<<<grid, 256, GEMM_SMEM>>>(x32, wq32, b_qkv, qkv,
                                            TOKENS, QKV_COLS, EMBED, 1);
    }
    // 2) Flash attention -> tf32 att
    {
        dim3 grid(BATCH * HEADS, SEQ / 128);
        flash_attn_tc<<<grid, 128, attn_smem>>>(qkv, att);
    }
    // 3) Output projection + bias -> fp32 out
    {
        dim3 grid(EMBED / 128, TOKENS / 128);
        gemm_tf32<<<grid, 256, GEMM_SMEM>>>(att, wp32, b_proj, out,
                                            TOKENS, EMBED, EMBED, 0);
    }
}